// round 16
// baseline (speedup 1.0000x reference)
#include <cuda_runtime.h>
#include <cuda_fp16.h>
#include <cstdint>

#define B_  32
#define W_  900
#define C_  256
#define MT_ 15          // 64-row m-tiles computed (tile 15 is all padding)
#define NSL 16          // norm partial slices

// ---------------- device scratch ----------------
__device__ float g_npart[2][B_][NSL][C_];             // partial sumsq
// staged fp16, layout [inp][b][tile128][kc 8][row 128][40], chunk=5120 halfs
__device__ __align__(128) __half g_sh[2ull * B_ * 8 * 8 * 128 * 40];

// ---------------- helpers ----------------
__device__ __forceinline__ uint32_t smem_u32(const void* p) {
    uint32_t a;
    asm("{ .reg .u64 t; cvta.to.shared.u64 t, %1; cvt.u32.u64 %0, t; }" : "=r"(a) : "l"(p));
    return a;
}
__device__ __forceinline__ void bulk_g2s(uint32_t dst, const void* src, uint32_t bytes,
                                         uint32_t mbar) {
    asm volatile("cp.async.bulk.shared::cta.global.mbarrier::complete_tx::bytes "
                 "[%0], [%1], %2, [%3];"
                 :: "r"(dst), "l"(src), "r"(bytes), "r"(mbar) : "memory");
}
#define MB_INIT(a, n) asm volatile("mbarrier.init.shared.b64 [%0], %1;" \
    :: "r"((uint32_t)(a)), "r"((uint32_t)(n)) : "memory")
#define MB_EXPECT_TX(a, n) asm volatile("mbarrier.arrive.expect_tx.shared.b64 _, [%0], %1;" \
    :: "r"((uint32_t)(a)), "r"((uint32_t)(n)) : "memory")
#define MB_WAIT(a, ph) do { \
    uint32_t _m = (uint32_t)(a), _p = (uint32_t)(ph), _d; \
    asm volatile("{\n\t.reg .pred p;\n\t" \
        "mbarrier.try_wait.parity.acquire.cta.shared::cta.b64 p, [%1], %2;\n\t" \
        "selp.b32 %0, 1, 0, p;\n\t}" : "=r"(_d) : "r"(_m), "r"(_p) : "memory"); \
    if (!_d) { \
        asm volatile("{\n\t.reg .pred P1;\n\t" \
            "W_%=:\n\t" \
            "mbarrier.try_wait.parity.acquire.cta.shared::cta.b64 P1, [%0], %1, 0x989680;\n\t" \
            "@P1 bra.uni D_%=;\n\t" \
            "bra.uni W_%=;\n\t" \
            "D_%=:\n\t}" :: "r"(_m), "r"(_p) : "memory"); \
    } } while (0)

#define NBAR_SYNC(id, n) asm volatile("bar.sync %0, %1;" :: "r"(id), "r"(n) : "memory")
#define NBAR_ARR(id, n)  asm volatile("bar.arrive %0, %1;" :: "r"(id), "r"(n) : "memory")

#define LDMX4(r0, r1, r2, r3, addr) asm volatile( \
    "ldmatrix.sync.aligned.m8n8.x4.shared.b16 {%0,%1,%2,%3}, [%4];" \
    : "=r"(r0), "=r"(r1), "=r"(r2), "=r"(r3) : "r"(addr))

__device__ __forceinline__ void mma16816(float* d, const uint32_t* a, const uint32_t* b) {
    asm volatile(
        "mma.sync.aligned.m16n8k16.row.col.f32.f16.f16.f32 "
        "{%0,%1,%2,%3}, {%4,%5,%6,%7}, {%8,%9}, {%0,%1,%2,%3};\n"
        : "+f"(d[0]), "+f"(d[1]), "+f"(d[2]), "+f"(d[3])
        : "r"(a[0]), "r"(a[1]), "r"(a[2]), "r"(a[3]), "r"(b[0]), "r"(b[1]));
}

// ---------------- kernel 1: partial sum-of-squares (+ zero d_out) ----------------
// grid 1024 = (inp<<9 | b<<4 | slice16); 57-row slices for higher MLP
__global__ void k_norms1(const float* __restrict__ x1, const float* __restrict__ x2,
                         float* __restrict__ out) {
    const int inp = blockIdx.x >> 9;
    const int b   = (blockIdx.x >> 4) & 31;
    const int sl  = blockIdx.x & 15;
    const float4* src = reinterpret_cast<const float4*>(inp ? x2 : x1);
    const int tid = threadIdx.x;
    const int c4 = tid & 63, ws = tid >> 6;
    const int w0 = sl * 57;
    const int wend = (w0 + 57 < W_) ? (w0 + 57) : W_;

    {   // zero output (k_corr accumulates atomically)
        const int i = blockIdx.x * 256 + tid;
        if (i < B_ * W_) out[i] = 0.f;
    }

    float4 s = make_float4(0.f, 0.f, 0.f, 0.f);
#pragma unroll 8
    for (int w = w0 + ws; w < wend; w += 4) {
        float4 v = src[((size_t)b * W_ + w) * 64 + c4];
        s.x += v.x * v.x; s.y += v.y * v.y; s.z += v.z * v.z; s.w += v.w * v.w;
    }
    __shared__ float4 red[256];
    red[tid] = s;
    __syncthreads();
    if (tid < 64) {
        float4 a = red[tid], b4 = red[tid + 64], c = red[tid + 128], d = red[tid + 192];
        float4 r;
        r.x = a.x + b4.x + c.x + d.x;
        r.y = a.y + b4.y + c.y + d.y;
        r.z = a.z + b4.z + c.z + d.z;
        r.w = a.w + b4.w + c.w + d.w;
        reinterpret_cast<float4*>(&g_npart[inp][b][sl][0])[c4] = r;
    }
}

// ---------------- kernel 2: stage fp16 both inputs (norm combine fused) --------
// grid 512 = (inp<<8 | b<<3 | tile)
__global__ __launch_bounds__(256) void k_stage(const float* __restrict__ x1,
                                               const float* __restrict__ x2) {
    __shared__ float h[256];
    const int inp  = blockIdx.x >> 8;
    const int b    = (blockIdx.x >> 3) & 31;
    const int tile = blockIdx.x & 7;
    const int tid  = threadIdx.x;
    {
        float s1 = 0.f, s2 = 0.f;
#pragma unroll
        for (int sl = 0; sl < NSL; sl++) {
            s1 += g_npart[0][b][sl][tid];
            s2 += g_npart[1][b][sl][tid];
        }
        // sqrt(invn1*invn2) = (s1*s2)^(-1/4)
        h[tid] = 1.f / sqrtf(sqrtf(fmaxf(s1, 1e-12f) * fmaxf(s2, 1e-12f)));
    }
    __syncthreads();

    const float2* src = reinterpret_cast<const float2*>(inp ? x2 : x1)
                      + (size_t)b * W_ * 128;
    __half* dst = g_sh + ((size_t)inp * 256 + b * 8 + tile) * 40960;

#pragma unroll 4
    for (int p = 0; p < 64; p++) {             // 16384 half2 = 128 rows x 128 cpairs
        const int idx = p * 256 + tid;
        const int row = idx >> 7, cp = idx & 127;
        const int w = tile * 128 + row;
        const int c = cp * 2;
        __half2 v2 = __float2half2_rn(0.f);
        if (w < W_) {
            float2 v = src[(size_t)w * 128 + cp];
            v2 = __floats2half2_rn(v.x * h[c], v.y * h[c + 1]);
        }
        const int kc = c >> 5, kl = c & 31;
        *reinterpret_cast<__half2*>(dst + kc * 5120 + row * 40 + kl) = v2;
    }
#pragma unroll
    for (int p = 0; p < 16; p++) {             // pad cols 32..39 -> zero
        const int idx = p * 256 + tid;
        const int row = idx >> 5, kc = (idx >> 2) & 7, q = idx & 3;
        *reinterpret_cast<__half2*>(dst + kc * 5120 + row * 40 + 32 + q * 2) =
            __float2half2_rn(0.f);
    }
}

// ---------------- kernel 3: fp16 GEMM 64x256 block, 32x64 warps (R14 mainloop) --
// smem: ctrl[0,1024) | A[1024,41984) 8x5120 | ring 2x20480 [41984,82944)
//       sG 32x132 f32 [82944,99840) | jacc [99840,103456)
#define SM_A    1024
#define SM_BR   41984
#define SM_SG   82944
#define SM_JACC 99840
#define SM_BYTES 103456
#define SG_S 132

__global__ __launch_bounds__(256, 2) void k_corr(float* __restrict__ out) {
    extern __shared__ float smf[];
    const uint32_t sbase = smem_u32(smf);
    const int tid = threadIdx.x, lane = tid & 31, wid = tid >> 5;
    const int gid = lane >> 2, tig = lane & 3;
    const int wm = wid >> 2, wn = wid & 3;      // 2x4 warps -> 32x64 tiles
    const int b = blockIdx.x / MT_, mt = blockIdx.x % MT_;   // 64-row m-tiles

    if (tid == 0) {
        MB_INIT(sbase + 0, 1);                  // A
        MB_INIT(sbase + 16, 1);                 // B stage 0
        MB_INIT(sbase + 32, 1);                 // B stage 1
    }
    __syncthreads();

    // A: 8 half-chunk slices (64 rows) of staged 128-row tile mt>>1
    const __half* srcA = g_sh + ((size_t)b * 8 + (mt >> 1)) * 40960 + (mt & 1) * 2560;
    const __half* srcB = g_sh + ((size_t)256 + b * 8) * 40960;
    if (tid == 0) {
        MB_EXPECT_TX(sbase + 0, 40960);
#pragma unroll
        for (int kc = 0; kc < 8; kc++)
            bulk_g2s(sbase + SM_A + kc * 5120, srcA + (size_t)kc * 5120, 5120u, sbase + 0);
        // pre-issue chunks c=0,1 (itp 0, kc 0/1); each = 2 sub-chunks (tiles 0,1)
#pragma unroll
        for (int c = 0; c < 2; c++) {
            MB_EXPECT_TX(sbase + 16 + c * 16, 20480);
            bulk_g2s(sbase + SM_BR + c * 20480,
                     srcB + (size_t)c * 5120, 10240u, sbase + 16 + c * 16);
            bulk_g2s(sbase + SM_BR + c * 20480 + 10240,
                     srcB + (size_t)(8 + c) * 5120, 10240u, sbase + 16 + c * 16);
        }
    }

    float* sG   = smf + (SM_SG >> 2);
    float* jacc = smf + (SM_JACC >> 2);
    for (int i = tid; i < W_; i += 256) jacc[i] = 0.f;

    // ldmatrix byte offsets (A within 5120B kc-chunk, B within 10240B sub-chunk)
    int aoff[2], boff[4];
#pragma unroll
    for (int mf = 0; mf < 2; mf++)
        aoff[mf] = (wm * 32 + mf * 16 + (lane & 15)) * 80 + (lane >> 4) * 16;
#pragma unroll
    for (int np = 0; np < 4; np++)
        boff[np] = ((wn & 1) * 64 + np * 16 + (lane >> 4) * 8 + (lane & 7)) * 80
                 + ((lane >> 3) & 1) * 16;
    const int hsub = (wn >> 1) * 10240;         // it sub-chunk select per warp

    MB_WAIT(sbase + 0, 0);       // A resident
    __syncthreads();             // jacc zeroed

    float acc[2][8][4];

#pragma unroll 1
    for (int g = 0; g < 32; g++) {             // itp = g>>3, kc = g&7
        const int s = g & 1;
        MB_WAIT(sbase + 16 + s * 16, (g >> 1) & 1);

        if ((g & 7) == 0) {
#pragma unroll
            for (int mf = 0; mf < 2; mf++)
#pragma unroll
                for (int nf = 0; nf < 8; nf++)
#pragma unroll
                    for (int r = 0; r < 4; r++) acc[mf][nf][r] = 0.f;
        }

        const uint32_t abase = sbase + SM_A + (g & 7) * 5120;
        const uint32_t bbase = sbase + SM_BR + s * 20480 + hsub;

#pragma unroll
        for (int ks = 0; ks < 2; ks++) {       // 2 k-steps of 16
            uint32_t af[2][4], bf[4][4];
#pragma unroll
            for (int mf = 0; mf < 2; mf++)
                LDMX4(af[mf][0], af[mf][1], af[mf][2], af[mf][3],
                      abase + aoff[mf] + ks * 32);
#pragma unroll
            for (int np = 0; np < 4; np++)
                LDMX4(bf[np][0], bf[np][1], bf[np][2], bf[np][3],
                      bbase + boff[np] + ks * 32);
#pragma unroll
            for (int np = 0; np < 4; np++)
#pragma unroll
                for (int q = 0; q < 2; q++)
#pragma unroll
                    for (int mf = 0; mf < 2; mf++)
                        mma16816(acc[mf][np * 2 + q], af[mf], &bf[np][q * 2]);
        }

        // consumption signal: warps 1-7 arrive (non-blocking); warp 0 syncs+reissues
        if (wid == 0) {
            NBAR_SYNC(2 + s, 256);
            if (tid == 0 && g + 2 < 32) {
                const int c2 = g + 2, itp2 = c2 >> 3, kc2 = c2 & 7;
                MB_EXPECT_TX(sbase + 16 + s * 16, 20480);
                bulk_g2s(sbase + SM_BR + s * 20480,
                         srcB + (size_t)(16 * itp2 + kc2) * 5120, 10240u,
                         sbase + 16 + s * 16);
                bulk_g2s(sbase + SM_BR + s * 20480 + 10240,
                         srcB + (size_t)(16 * itp2 + 8 + kc2) * 5120, 10240u,
                         sbase + 16 + s * 16);
            }
        } else {
            NBAR_ARR(2 + s, 256);
        }

        if ((g & 7) == 7) {
            const int itp = g >> 3;
            // 4 sub-passes: h = it half (warp wn>>1), p = m half (warp wm)
#pragma unroll
            for (int h = 0; h < 2; h++) {
#pragma unroll
                for (int p = 0; p < 2; p++) {
                    if (wm == p && (wn >> 1) == h) {
#pragma unroll
                        for (int mf = 0; mf < 2; mf++)
#pragma unroll
                            for (int nf = 0; nf < 8; nf++) {
                                const int row = mf * 16 + gid;   // 0..31 strip
                                const int col = (wn & 1) * 64 + nf * 8 + tig * 2;
                                *reinterpret_cast<float2*>(&sG[row * SG_S + col]) =
                                    make_float2(acc[mf][nf][0], acc[mf][nf][1]);
                                *reinterpret_cast<float2*>(&sG[(row + 8) * SG_S + col]) =
                                    make_float2(acc[mf][nf][2], acc[mf][nf][3]);
                            }
                    }
                    __syncthreads();
                    if (tid < 159) {
                        const int dd = tid - 127;   // r - c in strip, [-127, 31]
                        const int rlo = dd > 0 ? dd : 0;
                        const int rhi = (dd + 127 < 31) ? dd + 127 : 31;
                        float sAcc = 0.f;
                        for (int r = rlo; r <= rhi; r++)
                            sAcc += sG[r * SG_S + (r - dd)];
                        int t = 64 * mt + 32 * p - 128 * (2 * itp + h) + tid + 1223;
                        if (t >= 1800) t -= 1800;
                        if (t >= 900)  t -= 900;
                        jacc[t] += sAcc;
                    }
                    __syncthreads();
                }
            }
        }
    }

    __syncthreads();
    for (int i = tid; i < W_; i += 256)
        atomicAdd(&out[b * W_ + i], jacc[i]);
}

// ---------------- dummy: aligns ncu capture (idx 3) onto k_corr ----------------
__global__ void k_dummy() {}

// ---------------- launch ----------------
extern "C" void kernel_launch(void* const* d_in, const int* in_sizes, int n_in,
                              void* d_out, int out_size) {
    (void)in_sizes; (void)n_in; (void)out_size;
    const float* x1 = (const float*)d_in[0];
    const float* x2 = (const float*)d_in[1];
    float* out = (float*)d_out;

    cudaFuncSetAttribute(k_corr, cudaFuncAttributeMaxDynamicSharedMemorySize, SM_BYTES);

    k_norms1<<<1024, 256>>>(x1, x2, out);        // idx 0
    k_stage<<<512, 256>>>(x1, x2);               // idx 1
    k_dummy<<<1, 32>>>();                        // idx 2
    k_corr<<<B_ * MT_, 256, SM_BYTES>>>(out);    // idx 3  <- ncu captures this
}

// round 17
// speedup vs baseline: 1.0182x; 1.0182x over previous
#include <cuda_runtime.h>
#include <cuda_fp16.h>
#include <cstdint>

#define B_  32
#define W_  900
#define C_  256
#define MT_ 15          // 64-row m-tiles computed (tile 15 is all padding)
#define NSL 16          // norm partial slices

// ---------------- device scratch ----------------
__device__ float g_npart[2][B_][NSL][C_];             // partial sumsq
// staged fp16, layout [inp][b][tile128][kc 8][row 128][40], chunk=5120 halfs
__device__ __align__(128) __half g_sh[2ull * B_ * 8 * 8 * 128 * 40];

// ---------------- helpers ----------------
__device__ __forceinline__ uint32_t smem_u32(const void* p) {
    uint32_t a;
    asm("{ .reg .u64 t; cvta.to.shared.u64 t, %1; cvt.u32.u64 %0, t; }" : "=r"(a) : "l"(p));
    return a;
}
__device__ __forceinline__ void bulk_g2s(uint32_t dst, const void* src, uint32_t bytes,
                                         uint32_t mbar) {
    asm volatile("cp.async.bulk.shared::cta.global.mbarrier::complete_tx::bytes "
                 "[%0], [%1], %2, [%3];"
                 :: "r"(dst), "l"(src), "r"(bytes), "r"(mbar) : "memory");
}
#define MB_INIT(a, n) asm volatile("mbarrier.init.shared.b64 [%0], %1;" \
    :: "r"((uint32_t)(a)), "r"((uint32_t)(n)) : "memory")
#define MB_EXPECT_TX(a, n) asm volatile("mbarrier.arrive.expect_tx.shared.b64 _, [%0], %1;" \
    :: "r"((uint32_t)(a)), "r"((uint32_t)(n)) : "memory")
#define MB_WAIT(a, ph) do { \
    uint32_t _m = (uint32_t)(a), _p = (uint32_t)(ph), _d; \
    asm volatile("{\n\t.reg .pred p;\n\t" \
        "mbarrier.try_wait.parity.acquire.cta.shared::cta.b64 p, [%1], %2;\n\t" \
        "selp.b32 %0, 1, 0, p;\n\t}" : "=r"(_d) : "r"(_m), "r"(_p) : "memory"); \
    if (!_d) { \
        asm volatile("{\n\t.reg .pred P1;\n\t" \
            "W_%=:\n\t" \
            "mbarrier.try_wait.parity.acquire.cta.shared::cta.b64 P1, [%0], %1, 0x989680;\n\t" \
            "@P1 bra.uni D_%=;\n\t" \
            "bra.uni W_%=;\n\t" \
            "D_%=:\n\t}" :: "r"(_m), "r"(_p) : "memory"); \
    } } while (0)

#define NBAR_SYNC(id, n) asm volatile("bar.sync %0, %1;" :: "r"(id), "r"(n) : "memory")
#define NBAR_ARR(id, n)  asm volatile("bar.arrive %0, %1;" :: "r"(id), "r"(n) : "memory")

#define LDMX4(r0, r1, r2, r3, addr) asm volatile( \
    "ldmatrix.sync.aligned.m8n8.x4.shared.b16 {%0,%1,%2,%3}, [%4];" \
    : "=r"(r0), "=r"(r1), "=r"(r2), "=r"(r3) : "r"(addr))

__device__ __forceinline__ void mma16816(float* d, const uint32_t* a, const uint32_t* b) {
    asm volatile(
        "mma.sync.aligned.m16n8k16.row.col.f32.f16.f16.f32 "
        "{%0,%1,%2,%3}, {%4,%5,%6,%7}, {%8,%9}, {%0,%1,%2,%3};\n"
        : "+f"(d[0]), "+f"(d[1]), "+f"(d[2]), "+f"(d[3])
        : "r"(a[0]), "r"(a[1]), "r"(a[2]), "r"(a[3]), "r"(b[0]), "r"(b[1]));
}

// ---------------- kernel 1: partial sum-of-squares (+ zero d_out) ----------------
// grid 1024 = (inp<<9 | b<<4 | slice16); 57-row slices for higher MLP
__global__ void k_norms1(const float* __restrict__ x1, const float* __restrict__ x2,
                         float* __restrict__ out) {
    const int inp = blockIdx.x >> 9;
    const int b   = (blockIdx.x >> 4) & 31;
    const int sl  = blockIdx.x & 15;
    const float4* src = reinterpret_cast<const float4*>(inp ? x2 : x1);
    const int tid = threadIdx.x;
    const int c4 = tid & 63, ws = tid >> 6;
    const int w0 = sl * 57;
    const int wend = (w0 + 57 < W_) ? (w0 + 57) : W_;

    {   // zero output (k_corr accumulates atomically)
        const int i = blockIdx.x * 256 + tid;
        if (i < B_ * W_) out[i] = 0.f;
    }

    float4 s = make_float4(0.f, 0.f, 0.f, 0.f);
#pragma unroll 8
    for (int w = w0 + ws; w < wend; w += 4) {
        float4 v = src[((size_t)b * W_ + w) * 64 + c4];
        s.x += v.x * v.x; s.y += v.y * v.y; s.z += v.z * v.z; s.w += v.w * v.w;
    }
    __shared__ float4 red[256];
    red[tid] = s;
    __syncthreads();
    if (tid < 64) {
        float4 a = red[tid], b4 = red[tid + 64], c = red[tid + 128], d = red[tid + 192];
        float4 r;
        r.x = a.x + b4.x + c.x + d.x;
        r.y = a.y + b4.y + c.y + d.y;
        r.z = a.z + b4.z + c.z + d.z;
        r.w = a.w + b4.w + c.w + d.w;
        reinterpret_cast<float4*>(&g_npart[inp][b][sl][0])[c4] = r;
    }
}

// ---------------- kernel 2: stage fp16 both inputs (norm combine fused) --------
// grid 512 = (inp<<8 | b<<3 | tile)
__global__ __launch_bounds__(256) void k_stage(const float* __restrict__ x1,
                                               const float* __restrict__ x2) {
    __shared__ float h[256];
    const int inp  = blockIdx.x >> 8;
    const int b    = (blockIdx.x >> 3) & 31;
    const int tile = blockIdx.x & 7;
    const int tid  = threadIdx.x;
    {
        float s1 = 0.f, s2 = 0.f;
#pragma unroll
        for (int sl = 0; sl < NSL; sl++) {
            s1 += g_npart[0][b][sl][tid];
            s2 += g_npart[1][b][sl][tid];
        }
        // sqrt(invn1*invn2) = (s1*s2)^(-1/4)
        h[tid] = 1.f / sqrtf(sqrtf(fmaxf(s1, 1e-12f) * fmaxf(s2, 1e-12f)));
    }
    __syncthreads();

    const float2* src = reinterpret_cast<const float2*>(inp ? x2 : x1)
                      + (size_t)b * W_ * 128;
    __half* dst = g_sh + ((size_t)inp * 256 + b * 8 + tile) * 40960;

#pragma unroll 4
    for (int p = 0; p < 64; p++) {             // 16384 half2 = 128 rows x 128 cpairs
        const int idx = p * 256 + tid;
        const int row = idx >> 7, cp = idx & 127;
        const int w = tile * 128 + row;
        const int c = cp * 2;
        __half2 v2 = __float2half2_rn(0.f);
        if (w < W_) {
            float2 v = src[(size_t)w * 128 + cp];
            v2 = __floats2half2_rn(v.x * h[c], v.y * h[c + 1]);
        }
        const int kc = c >> 5, kl = c & 31;
        *reinterpret_cast<__half2*>(dst + kc * 5120 + row * 40 + kl) = v2;
    }
#pragma unroll
    for (int p = 0; p < 16; p++) {             // pad cols 32..39 -> zero
        const int idx = p * 256 + tid;
        const int row = idx >> 5, kc = (idx >> 2) & 7, q = idx & 3;
        *reinterpret_cast<__half2*>(dst + kc * 5120 + row * 40 + 32 + q * 2) =
            __float2half2_rn(0.f);
    }
}

// ---------------- kernel 3: fp16 GEMM 64x256 block, 32x64 warps ----------------
// smem: ctrl[0,1024) | A[1024,41984) 8x5120 | ring 2x20480 [41984,82944)
//       sG 32x132 f32 [82944,99840) | jacc [99840,103456)
#define SM_A    1024
#define SM_BR   41984
#define SM_SG   82944
#define SM_JACC 99840
#define SM_BYTES 103456
#define SG_S 132

__global__ __launch_bounds__(256, 2) void k_corr(float* __restrict__ out) {
    extern __shared__ float smf[];
    const uint32_t sbase = smem_u32(smf);
    const int tid = threadIdx.x, lane = tid & 31, wid = tid >> 5;
    const int gid = lane >> 2, tig = lane & 3;
    const int wm = wid >> 2, wn = wid & 3;      // 2x4 warps -> 32x64 tiles
    const int b = blockIdx.x / MT_, mt = blockIdx.x % MT_;   // 64-row m-tiles

    if (tid == 0) {
        MB_INIT(sbase + 0, 1);                  // A
        MB_INIT(sbase + 16, 1);                 // B stage 0
        MB_INIT(sbase + 32, 1);                 // B stage 1
    }
    __syncthreads();

    // A: 8 half-chunk slices (64 rows) of staged 128-row tile mt>>1
    const __half* srcA = g_sh + ((size_t)b * 8 + (mt >> 1)) * 40960 + (mt & 1) * 2560;
    const __half* srcB = g_sh + ((size_t)256 + b * 8) * 40960;
    if (tid == 0) {
        MB_EXPECT_TX(sbase + 0, 40960);
#pragma unroll
        for (int kc = 0; kc < 8; kc++)
            bulk_g2s(sbase + SM_A + kc * 5120, srcA + (size_t)kc * 5120, 5120u, sbase + 0);
        // pre-issue chunks c=0,1 (itp 0, kc 0/1); each = 2 sub-chunks (tiles 0,1)
#pragma unroll
        for (int c = 0; c < 2; c++) {
            MB_EXPECT_TX(sbase + 16 + c * 16, 20480);
            bulk_g2s(sbase + SM_BR + c * 20480,
                     srcB + (size_t)c * 5120, 10240u, sbase + 16 + c * 16);
            bulk_g2s(sbase + SM_BR + c * 20480 + 10240,
                     srcB + (size_t)(8 + c) * 5120, 10240u, sbase + 16 + c * 16);
        }
    }

    float* sG   = smf + (SM_SG >> 2);
    float* jacc = smf + (SM_JACC >> 2);
    for (int i = tid; i < W_; i += 256) jacc[i] = 0.f;

    // ldmatrix byte offsets (A within 5120B kc-chunk, B within 10240B sub-chunk)
    int aoff[2], boff[4];
#pragma unroll
    for (int mf = 0; mf < 2; mf++)
        aoff[mf] = (wm * 32 + mf * 16 + (lane & 15)) * 80 + (lane >> 4) * 16;
#pragma unroll
    for (int np = 0; np < 4; np++)
        boff[np] = ((wn & 1) * 64 + np * 16 + (lane >> 4) * 8 + (lane & 7)) * 80
                 + ((lane >> 3) & 1) * 16;
    const int hsub = (wn >> 1) * 10240;         // it sub-chunk select per warp

    MB_WAIT(sbase + 0, 0);       // A resident
    __syncthreads();             // jacc zeroed

    float acc[2][8][4];

#pragma unroll 1
    for (int g = 0; g < 32; g++) {             // itp = g>>3, kc = g&7
        const int s = g & 1;
        MB_WAIT(sbase + 16 + s * 16, (g >> 1) & 1);

        if ((g & 7) == 0) {
#pragma unroll
            for (int mf = 0; mf < 2; mf++)
#pragma unroll
                for (int nf = 0; nf < 8; nf++)
#pragma unroll
                    for (int r = 0; r < 4; r++) acc[mf][nf][r] = 0.f;
        }

        const uint32_t abase = sbase + SM_A + (g & 7) * 5120;
        const uint32_t bbase = sbase + SM_BR + s * 20480 + hsub;

#pragma unroll
        for (int ks = 0; ks < 2; ks++) {       // 2 k-steps of 16
            uint32_t af[2][4], bf[4][4];
#pragma unroll
            for (int mf = 0; mf < 2; mf++)
                LDMX4(af[mf][0], af[mf][1], af[mf][2], af[mf][3],
                      abase + aoff[mf] + ks * 32);
#pragma unroll
            for (int np = 0; np < 4; np++)
                LDMX4(bf[np][0], bf[np][1], bf[np][2], bf[np][3],
                      bbase + boff[np] + ks * 32);
#pragma unroll
            for (int np = 0; np < 4; np++)
#pragma unroll
                for (int q = 0; q < 2; q++)
#pragma unroll
                    for (int mf = 0; mf < 2; mf++)
                        mma16816(acc[mf][np * 2 + q], af[mf], &bf[np][q * 2]);
        }

        // consumption signal: warps 1-7 arrive (non-blocking); warp 0 syncs+reissues
        if (wid == 0) {
            NBAR_SYNC(2 + s, 256);
            if (tid == 0 && g + 2 < 32) {
                const int c2 = g + 2, itp2 = c2 >> 3, kc2 = c2 & 7;
                MB_EXPECT_TX(sbase + 16 + s * 16, 20480);
                bulk_g2s(sbase + SM_BR + s * 20480,
                         srcB + (size_t)(16 * itp2 + kc2) * 5120, 10240u,
                         sbase + 16 + s * 16);
                bulk_g2s(sbase + SM_BR + s * 20480 + 10240,
                         srcB + (size_t)(16 * itp2 + 8 + kc2) * 5120, 10240u,
                         sbase + 16 + s * 16);
            }
        } else {
            NBAR_ARR(2 + s, 256);
        }

        if ((g & 7) == 7) {
            const int itp = g >> 3;
            // 4 sub-passes: h = it half (warp wn>>1), p = m half (warp wm)
#pragma unroll
            for (int h = 0; h < 2; h++) {
#pragma unroll
                for (int p = 0; p < 2; p++) {
                    // mt==14: m-local rows >= 4 are zero-padding -> p==1 all zero
                    if (mt == MT_ - 1 && p == 1) continue;
                    if (wm == p && (wn >> 1) == h) {
#pragma unroll
                        for (int mf = 0; mf < 2; mf++)
#pragma unroll
                            for (int nf = 0; nf < 8; nf++) {
                                const int row = mf * 16 + gid;   // 0..31 strip
                                const int col = (wn & 1) * 64 + nf * 8 + tig * 2;
                                *reinterpret_cast<float2*>(&sG[row * SG_S + col]) =
                                    make_float2(acc[mf][nf][0], acc[mf][nf][1]);
                                *reinterpret_cast<float2*>(&sG[(row + 8) * SG_S + col]) =
                                    make_float2(acc[mf][nf][2], acc[mf][nf][3]);
                            }
                    }
                    __syncthreads();
                    if (tid < 159) {
                        const int dd = tid - 127;   // r - c in strip, [-127, 31]
                        const int rlo = dd > 0 ? dd : 0;
                        int rhi = (dd + 127 < 31) ? dd + 127 : 31;
                        if (mt == MT_ - 1) rhi = rhi < 3 ? rhi : 3;          // m >= 900
                        if (itp == 3 && h == 1) {                            // it == 7
                            const int r2 = dd + 3;                           // i >= 900
                            rhi = rhi < r2 ? rhi : r2;
                        }
                        float sAcc = 0.f;
                        for (int r = rlo; r <= rhi; r++)
                            sAcc += sG[r * SG_S + (r - dd)];
                        int t = 64 * mt + 32 * p - 128 * (2 * itp + h) + tid + 1223;
                        if (t >= 1800) t -= 1800;
                        if (t >= 900)  t -= 900;
                        jacc[t] += sAcc;
                    }
                    __syncthreads();
                }
            }
        }
    }

    __syncthreads();
    for (int i = tid; i < W_; i += 256)
        atomicAdd(&out[b * W_ + i], jacc[i]);
}

// ---------------- launch ----------------
extern "C" void kernel_launch(void* const* d_in, const int* in_sizes, int n_in,
                              void* d_out, int out_size) {
    (void)in_sizes; (void)n_in; (void)out_size;
    const float* x1 = (const float*)d_in[0];
    const float* x2 = (const float*)d_in[1];
    float* out = (float*)d_out;

    cudaFuncSetAttribute(k_corr, cudaFuncAttributeMaxDynamicSharedMemorySize, SM_BYTES);

    k_norms1<<<1024, 256>>>(x1, x2, out);        // idx 0
    k_stage<<<512, 256>>>(x1, x2);               // idx 1
    k_corr<<<B_ * MT_, 256, SM_BYTES>>>(out);    // idx 2
}